// round 14
// baseline (speedup 1.0000x reference)
#include <cuda_runtime.h>
#include <math.h>

#define BB   16
#define TT   3300
#define RNN  512
#define DMEL 80
#define NCTA 128

// ---------------- device scratch (allocation-free) --------------------------
__device__ float g_m2[BB*DMEL*400];
__device__ float g_mu[(size_t)TT*BB*DMEL];      // [n=t*16+b][80]
__device__ float g_wT[512*1536];                // g_wT[d][m] = w_ih[m][d]
__device__ float g_xp[(size_t)TT*BB*1536];      // x_proj rows n
__device__ float g_hs[(size_t)TT*BB*RNN];       // GRU hidden history
__device__ float g_y1[(size_t)TT*BB*RNN];       // fc1 out
__device__ float g_hbuf[2][BB*RNN];             // double-buffered h
__device__ unsigned g_flags[NCTA*32];           // per-CTA arrival flags, 128B stride
__device__ unsigned g_go;                       // broadcast step flag

// ---------------- fused prep: up1∘up2 direct + w_ih transpose + gru init ----
__global__ void pre_k(const float* __restrict__ mels,
                      const float* __restrict__ k0v,
                      const float* __restrict__ k1v,
                      const float* __restrict__ w_ih)
{
    int idx = blockIdx.x*256 + threadIdx.x;
    if (idx < BB*DMEL*400){                       // g_m2 = conv(rep(conv(rep(mels))))
        int w = idx % 400, bc = idx / 400;
        float s = 0.f;
#pragma unroll
        for (int i = 0; i < 11; i++){
            int u = w - 5 + i;
            if (u >= 0 && u < 400){
                int um = u / 5;
                float m1v = 0.f;
#pragma unroll
                for (int j = 0; j < 11; j++){
                    int p = um - 5 + j;
                    if (p >= 0 && p < 80) m1v += mels[bc*16 + p/5] * k0v[j];
                }
                s += m1v * k1v[i];
            }
        }
        g_m2[idx] = s;
    }
    if (idx < 512*1536){                          // w_ih one-hot-part transpose
        int d = idx / 1536, m = idx - d*1536;
        g_wT[idx] = w_ih[(size_t)m*592 + d];
    }
    if (idx < BB*RNN) g_hbuf[0][idx] = 0.f;       // GRU init
    if (idx < NCTA*32) g_flags[idx] = 0u;
    if (idx == BB*RNN) g_go = 0u;
}

// stage 3 fused with crop (INDENT=550) + transpose to [t][b][f]
__global__ void up3_k(const float* __restrict__ kern){
    int idx = blockIdx.x*256 + threadIdx.x;
    if (idx >= TT*BB*DMEL) return;
    int f = idx % 80, r = idx / 80;
    int b = r & 15, t = r >> 4;
    int bc = b*80 + f;
    float s = 0.f;
#pragma unroll
    for (int i = 0; i < 23; i++)
        s += g_m2[bc*400 + (t + 539 + i)/11] * kern[i];
    g_mu[idx] = s;
}

// ---------------- double-buffered tiled fp32 GEMM (known-good) --------------
__global__ __launch_bounds__(256) void gemm_k(
    int aSel, const float* __restrict__ W, int ldw, int wOff,
    const float* __restrict__ bias, int cSel, float* __restrict__ Cext,
    int M, int K, int mode, int useGather, const int* __restrict__ xIdx)
{
    const float* A = (aSel==0) ? g_mu : (aSel==1) ? g_hs : g_y1;
    float* C = (cSel==0) ? g_xp : (cSel==1) ? g_y1 : Cext;
    __shared__ __align__(16) float sA[2][16][68];
    __shared__ __align__(16) float sB[2][16][68];
    __shared__ int sX[64];
    int n0 = blockIdx.y << 6, m0 = blockIdx.x << 6;
    int tid = threadIdx.x;
    int row = tid >> 2, quad = tid & 3;
    int tx = tid & 15, ty = tid >> 4;
    float acc[4][4];
#pragma unroll
    for (int i = 0; i < 4; i++)
#pragma unroll
        for (int j = 0; j < 4; j++) acc[i][j] = 0.f;

    if (useGather && tid < 64){
        int n = n0 + tid;
        sX[tid] = xIdx[(n & 15)*TT + (n >> 4)];
    }
    const float* aBase = &A[(size_t)(n0 + row)*K + (quad << 2)];
    const float* bBase = &W[(size_t)(m0 + row)*ldw + wOff + (quad << 2)];
    float4 ra = *(const float4*)aBase;
    float4 rb = *(const float4*)bBase;
    int buf = 0;
    for (int k0 = 0; k0 < K; k0 += 16){
        int c = quad << 2;
        sA[buf][c+0][row] = ra.x; sA[buf][c+1][row] = ra.y;
        sA[buf][c+2][row] = ra.z; sA[buf][c+3][row] = ra.w;
        sB[buf][c+0][row] = rb.x; sB[buf][c+1][row] = rb.y;
        sB[buf][c+2][row] = rb.z; sB[buf][c+3][row] = rb.w;
        __syncthreads();
        if (k0 + 16 < K){
            ra = *(const float4*)(aBase + k0 + 16);
            rb = *(const float4*)(bBase + k0 + 16);
        }
#pragma unroll
        for (int k = 0; k < 16; k++){
            float4 a = *(const float4*)&sA[buf][k][ty << 2];
            float4 b = *(const float4*)&sB[buf][k][tx << 2];
            float av[4] = {a.x, a.y, a.z, a.w};
            float bv[4] = {b.x, b.y, b.z, b.w};
#pragma unroll
            for (int i = 0; i < 4; i++)
#pragma unroll
                for (int j = 0; j < 4; j++) acc[i][j] += av[i]*bv[j];
        }
        buf ^= 1;
    }
    float4 bs = *(const float4*)&bias[m0 + (tx << 2)];
    float bb[4] = {bs.x, bs.y, bs.z, bs.w};
#pragma unroll
    for (int i = 0; i < 4; i++){
        int n = n0 + (ty << 2) + i;
        float o[4];
#pragma unroll
        for (int j = 0; j < 4; j++) o[j] = acc[i][j] + bb[j];
        if (useGather){
            const float* wr = &g_wT[(size_t)sX[(ty << 2) + i]*1536 + m0 + (tx << 2)];
#pragma unroll
            for (int j = 0; j < 4; j++) o[j] += wr[j];
        }
        if (mode == 1)
#pragma unroll
            for (int j = 0; j < 4; j++) o[j] = fmaxf(o[j], 0.f);
        size_t rowc = (mode == 2) ? ((size_t)(n & 15)*TT + (n >> 4)) : (size_t)n;
        *(float4*)&C[rowc*M + m0 + (tx << 2)] = make_float4(o[0], o[1], o[2], o[3]);
    }
}

// ---------------- persistent GRU: batch-blocked, smem-staged h --------------
// CTA = (16 units x 4 batches). ub = bid&31 -> units [ub*16, +16); bb = bid>>5
// -> batches [bb*4, +4). Warp = (kh in 0..1, rb in 0..3): 12 rows
// (3 gates x 4 units, units rb*4..rb*4+3) over k-half kh.
__device__ __forceinline__ unsigned long long pk2(unsigned x, unsigned y){
    unsigned long long r;
    asm("mov.b64 %0, {%1, %2};" : "=l"(r) : "r"(x), "r"(y));
    return r;
}

__global__ __launch_bounds__(256) void gru_k(const float* __restrict__ w_hh,
                                             const float* __restrict__ b_hh)
{
    __shared__ float hstage[4*512];         // h for this CTA's 4 batches (8KB)
    __shared__ float part[2*48*32];         // [kh][row_flat][b*8+q] (12KB)
    int tid = threadIdx.x;
    int lane = tid & 31, warp = tid >> 5;
    int kh = warp & 1, rb = warp >> 1;          // k-half, row-block
    int ub = blockIdx.x & 31, bb = blockIdx.x >> 5;
    int j0 = ub*16, b0 = bb*4;
    int kbase = kh*256 + lane*8;
    int gu = tid & 15, gb = tid >> 4;           // gate mapping (tid < 64)

    // W slice: 12 rows (gate = r'>>2, unit = rb*4 + (r'&3)), 8 k-floats/lane
    unsigned long long wp[12][4];
#pragma unroll
    for (int r = 0; r < 12; r++){
        int wrow = (r >> 2)*512 + j0 + rb*4 + (r & 3);
        const uint4* p = (const uint4*)&w_hh[(size_t)wrow*512 + kbase];
        uint4 q0 = p[0], q1 = p[1];
        wp[r][0] = pk2(q0.x, q0.y); wp[r][1] = pk2(q0.z, q0.w);
        wp[r][2] = pk2(q1.x, q1.y); wp[r][3] = pk2(q1.z, q1.w);
    }
    float brr = 0.f, bzz = 0.f, bnn = 0.f, xr = 0.f, xz = 0.f, xn = 0.f;
    if (tid < 64){
        brr = b_hh[j0 + gu]; bzz = b_hh[512 + j0 + gu]; bnn = b_hh[1024 + j0 + gu];
        const float* xp = &g_xp[(size_t)(b0 + gb)*1536 + j0 + gu];   // t = 0
        xr = __ldg(xp); xz = __ldg(xp + 512); xn = __ldg(xp + 1024);
    }

    for (int t = 0; t < TT; t++){
        const float* hb = g_hbuf[t & 1];
        // stage h (4 batches x 512) into smem: warps 0,1 (one per k-half)
        if (warp < 2){
#pragma unroll
            for (int i = 0; i < 8; i++){
                int q = lane + i*32;              // uint4 id 0..255 in this half
                int b = q >> 6, k4 = (q & 63)*4;  // batch, float offset in half
                uint4 v = __ldcg((const uint4*)&hb[(b0 + b)*512 + kh*256 + k4]);
                *(uint4*)&hstage[b*512 + kh*256 + k4] = v;
            }
        }
        __syncthreads();

        // per-thread h operands from smem (reused across 12 rows)
        unsigned long long hp[4][4];
#pragma unroll
        for (int b = 0; b < 4; b++){
            float4 v0 = *(const float4*)&hstage[b*512 + kbase];
            float4 v1 = *(const float4*)&hstage[b*512 + kbase + 4];
            hp[b][0] = pk2(__float_as_uint(v0.x), __float_as_uint(v0.y));
            hp[b][1] = pk2(__float_as_uint(v0.z), __float_as_uint(v0.w));
            hp[b][2] = pk2(__float_as_uint(v1.x), __float_as_uint(v1.y));
            hp[b][3] = pk2(__float_as_uint(v1.z), __float_as_uint(v1.w));
        }

#pragma unroll
        for (int r = 0; r < 12; r++)
#pragma unroll
            for (int b = 0; b < 4; b++){
                unsigned long long a2;
                asm("mul.rn.f32x2 %0, %1, %2;"     : "=l"(a2) : "l"(wp[r][0]), "l"(hp[b][0]));
                asm("fma.rn.f32x2 %0, %1, %2, %0;" : "+l"(a2) : "l"(wp[r][1]), "l"(hp[b][1]));
                asm("fma.rn.f32x2 %0, %1, %2, %0;" : "+l"(a2) : "l"(wp[r][2]), "l"(hp[b][2]));
                asm("fma.rn.f32x2 %0, %1, %2, %0;" : "+l"(a2) : "l"(wp[r][3]), "l"(hp[b][3]));
                float lo, hi;
                asm("mov.b64 {%0, %1}, %2;" : "=f"(lo), "=f"(hi) : "l"(a2));
                float v = lo + hi;
                v += __shfl_xor_sync(0xffffffffu, v, 1);
                v += __shfl_xor_sync(0xffffffffu, v, 2);
                if ((lane & 3) == 0)
                    part[(kh*48 + rb*12 + r)*32 + b*8 + (lane >> 2)] = v;
            }
        __syncthreads();

        if (tid < 64){
            float d[3];
#pragma unroll
            for (int g = 0; g < 3; g++){
                int rf = (gu >> 2)*12 + g*4 + (gu & 3);
                const float4* p0 = (const float4*)&part[rf*32 + gb*8];
                const float4* p1 = (const float4*)&part[(48 + rf)*32 + gb*8];
                float4 a = p0[0], b4 = p0[1], c = p1[0], e = p1[1];
                d[g] = ((a.x + a.y) + (a.z + a.w)) + ((b4.x + b4.y) + (b4.z + b4.w))
                     + ((c.x + c.y) + (c.z + c.w)) + ((e.x + e.y) + (e.z + e.w));
            }
            float hold = hstage[gb*512 + j0 + gu];
            float rg = 1.f/(1.f + expf(-(xr + d[0] + brr)));
            float zg = 1.f/(1.f + expf(-(xz + d[1] + bzz)));
            float ng = tanhf(xn + rg*(d[2] + bnn));
            float hnew = (1.f - zg)*ng + zg*hold;
            g_hbuf[(t + 1) & 1][(b0 + gb)*512 + j0 + gu] = hnew;
            g_hs[((size_t)t*16 + b0 + gb)*512 + j0 + gu] = hnew;
            int tn = (t + 1 < TT) ? t + 1 : t;
            const float* xp = &g_xp[(size_t)(tn*16 + b0 + gb)*1536 + j0 + gu];
            xr = __ldg(xp); xz = __ldg(xp + 512); xn = __ldg(xp + 1024);
        }
        __syncthreads();
        // ---- flag barrier: distinct-line release stores; CTA0 detects in
        // parallel (128 pollers, one line each), then releases g_go ----
        if (tid == 0)
            asm volatile("st.release.gpu.global.u32 [%0], %1;"
                         :: "l"(&g_flags[blockIdx.x*32]), "r"((unsigned)(t + 1)) : "memory");
        if (blockIdx.x == 0){
            if (tid < NCTA){
                unsigned v;
                do {
                    asm volatile("ld.acquire.gpu.global.u32 %0, [%1];"
                                 : "=r"(v) : "l"(&g_flags[tid*32]) : "memory");
                } while (v < (unsigned)(t + 1));
            }
            __syncthreads();
            if (tid == 0)
                asm volatile("st.release.gpu.global.u32 [%0], %1;"
                             :: "l"(&g_go), "r"((unsigned)(t + 1)) : "memory");
        } else if (tid == 0){
            unsigned v;
            while (true){
                asm volatile("ld.acquire.gpu.global.u32 %0, [%1];"
                             : "=r"(v) : "l"(&g_go) : "memory");
                if (v >= (unsigned)(t + 1)) break;
                __nanosleep(64);
            }
        }
        __syncthreads();
    }
}

// ---------------- launch ----------------------------------------------------
extern "C" void kernel_launch(void* const* d_in, const int* in_sizes, int n_in,
                              void* d_out, int out_size)
{
    const int*   x    = (const int*)  d_in[0];
    const float* mels = (const float*)d_in[1];
    const float* k0   = (const float*)d_in[2];
    const float* k1   = (const float*)d_in[3];
    const float* k2   = (const float*)d_in[4];
    const float* w_ih = (const float*)d_in[5];
    const float* w_hh = (const float*)d_in[6];
    const float* b_ih = (const float*)d_in[7];
    const float* b_hh = (const float*)d_in[8];
    const float* fc1w = (const float*)d_in[9];
    const float* fc1b = (const float*)d_in[10];
    const float* fc2w = (const float*)d_in[11];
    const float* fc2b = (const float*)d_in[12];
    float* out = (float*)d_out;

    pre_k<<<3072, 256>>>(mels, k0, k1, w_ih);                 // 1
    up3_k<<<16500, 256>>>(k2);                                // 2
    gemm_k<<<dim3(24, 825), 256>>>(0, w_ih, 592, 512, b_ih,   // 3: x_proj
                                   0, nullptr, 1536, 80, 0, 1, x);
    gru_k<<<NCTA, 256>>>(w_hh, b_hh);                         // 4  <- profiled slot
    gemm_k<<<dim3(8, 825), 256>>>(1, fc1w, 512, 0, fc1b,      // 5: fc1 (relu)
                                  1, nullptr, 512, 512, 1, 0, nullptr);
    gemm_k<<<dim3(8, 825), 256>>>(2, fc2w, 512, 0, fc2b,      // 6: fc2 (permuted out)
                                  2, out, 512, 512, 2, 0, nullptr);
}

// round 15
// speedup vs baseline: 1.6997x; 1.6997x over previous
#include <cuda_runtime.h>
#include <math.h>

#define BB   16
#define TT   3300
#define RNN  512
#define DMEL 80
#define NCTA 128

// ---------------- device scratch (allocation-free) --------------------------
__device__ float g_m2[BB*DMEL*400];
__device__ float g_mu[(size_t)TT*BB*DMEL];      // [n=t*16+b][80]
__device__ float g_wT[512*1536];                // g_wT[d][m] = w_ih[m][d]
__device__ float g_xp[(size_t)TT*BB*1536];      // x_proj rows n
__device__ float g_hs[(size_t)TT*BB*RNN];       // GRU hidden history
__device__ float g_y1[(size_t)TT*BB*RNN];       // fc1 out
__device__ float g_hbuf[2][BB*RNN];             // double-buffered h
__device__ unsigned g_bar;                      // monotonic arrival counter

// ---------------- fused prep: up1∘up2 direct + w_ih transpose + gru init ----
__global__ void pre_k(const float* __restrict__ mels,
                      const float* __restrict__ k0v,
                      const float* __restrict__ k1v,
                      const float* __restrict__ w_ih)
{
    int idx = blockIdx.x*256 + threadIdx.x;
    if (idx < BB*DMEL*400){                       // g_m2 = conv(rep(conv(rep(mels))))
        int w = idx % 400, bc = idx / 400;
        float s = 0.f;
#pragma unroll
        for (int i = 0; i < 11; i++){
            int u = w - 5 + i;
            if (u >= 0 && u < 400){
                int um = u / 5;
                float m1v = 0.f;
#pragma unroll
                for (int j = 0; j < 11; j++){
                    int p = um - 5 + j;
                    if (p >= 0 && p < 80) m1v += mels[bc*16 + p/5] * k0v[j];
                }
                s += m1v * k1v[i];
            }
        }
        g_m2[idx] = s;
    }
    if (idx < 512*1536){                          // w_ih one-hot-part transpose
        int d = idx / 1536, m = idx - d*1536;
        g_wT[idx] = w_ih[(size_t)m*592 + d];
    }
    if (idx < BB*RNN) g_hbuf[0][idx] = 0.f;       // GRU init
    if (idx == BB*RNN) g_bar = 0u;
}

// stage 3 fused with crop (INDENT=550) + transpose to [t][b][f]
__global__ void up3_k(const float* __restrict__ kern){
    int idx = blockIdx.x*256 + threadIdx.x;
    if (idx >= TT*BB*DMEL) return;
    int f = idx % 80, r = idx / 80;
    int b = r & 15, t = r >> 4;
    int bc = b*80 + f;
    float s = 0.f;
#pragma unroll
    for (int i = 0; i < 23; i++)
        s += g_m2[bc*400 + (t + 539 + i)/11] * kern[i];
    g_mu[idx] = s;
}

// ---------------- double-buffered tiled fp32 GEMM (known-good) --------------
__global__ __launch_bounds__(256) void gemm_k(
    int aSel, const float* __restrict__ W, int ldw, int wOff,
    const float* __restrict__ bias, int cSel, float* __restrict__ Cext,
    int M, int K, int mode, int useGather, const int* __restrict__ xIdx)
{
    const float* A = (aSel==0) ? g_mu : (aSel==1) ? g_hs : g_y1;
    float* C = (cSel==0) ? g_xp : (cSel==1) ? g_y1 : Cext;
    __shared__ __align__(16) float sA[2][16][68];
    __shared__ __align__(16) float sB[2][16][68];
    __shared__ int sX[64];
    int n0 = blockIdx.y << 6, m0 = blockIdx.x << 6;
    int tid = threadIdx.x;
    int row = tid >> 2, quad = tid & 3;
    int tx = tid & 15, ty = tid >> 4;
    float acc[4][4];
#pragma unroll
    for (int i = 0; i < 4; i++)
#pragma unroll
        for (int j = 0; j < 4; j++) acc[i][j] = 0.f;

    if (useGather && tid < 64){
        int n = n0 + tid;
        sX[tid] = xIdx[(n & 15)*TT + (n >> 4)];
    }
    const float* aBase = &A[(size_t)(n0 + row)*K + (quad << 2)];
    const float* bBase = &W[(size_t)(m0 + row)*ldw + wOff + (quad << 2)];
    float4 ra = *(const float4*)aBase;
    float4 rb = *(const float4*)bBase;
    int buf = 0;
    for (int k0 = 0; k0 < K; k0 += 16){
        int c = quad << 2;
        sA[buf][c+0][row] = ra.x; sA[buf][c+1][row] = ra.y;
        sA[buf][c+2][row] = ra.z; sA[buf][c+3][row] = ra.w;
        sB[buf][c+0][row] = rb.x; sB[buf][c+1][row] = rb.y;
        sB[buf][c+2][row] = rb.z; sB[buf][c+3][row] = rb.w;
        __syncthreads();
        if (k0 + 16 < K){
            ra = *(const float4*)(aBase + k0 + 16);
            rb = *(const float4*)(bBase + k0 + 16);
        }
#pragma unroll
        for (int k = 0; k < 16; k++){
            float4 a = *(const float4*)&sA[buf][k][ty << 2];
            float4 b = *(const float4*)&sB[buf][k][tx << 2];
            float av[4] = {a.x, a.y, a.z, a.w};
            float bv[4] = {b.x, b.y, b.z, b.w};
#pragma unroll
            for (int i = 0; i < 4; i++)
#pragma unroll
                for (int j = 0; j < 4; j++) acc[i][j] += av[i]*bv[j];
        }
        buf ^= 1;
    }
    float4 bs = *(const float4*)&bias[m0 + (tx << 2)];
    float bb[4] = {bs.x, bs.y, bs.z, bs.w};
#pragma unroll
    for (int i = 0; i < 4; i++){
        int n = n0 + (ty << 2) + i;
        float o[4];
#pragma unroll
        for (int j = 0; j < 4; j++) o[j] = acc[i][j] + bb[j];
        if (useGather){
            const float* wr = &g_wT[(size_t)sX[(ty << 2) + i]*1536 + m0 + (tx << 2)];
#pragma unroll
            for (int j = 0; j < 4; j++) o[j] += wr[j];
        }
        if (mode == 1)
#pragma unroll
            for (int j = 0; j < 4; j++) o[j] = fmaxf(o[j], 0.f);
        size_t rowc = (mode == 2) ? ((size_t)(n & 15)*TT + (n >> 4)) : (size_t)n;
        *(float4*)&C[rowc*M + m0 + (tx << 2)] = make_float4(o[0], o[1], o[2], o[3]);
    }
}

// ---------------- persistent GRU (exact R7 best-measured design) ------------
__device__ __forceinline__ unsigned long long pk2(unsigned x, unsigned y){
    unsigned long long r;
    asm("mov.b64 %0, {%1, %2};" : "=l"(r) : "r"(x), "r"(y));
    return r;
}

__global__ __launch_bounds__(256) void gru_k(const float* __restrict__ w_hh,
                                             const float* __restrict__ b_hh)
{
    __shared__ float part[2*12*16*8];   // [kh][row][batch][8 partials] = 12KB
    int tid = threadIdx.x, j0 = blockIdx.x*4;
    int lane = tid & 31, warp = tid >> 5;
    int kh = warp & 1, bg = warp >> 1;          // k-half, batch group of 4
    int kbase = kh*256 + lane*8;                // 8 k-floats per lane
    int gu = tid >> 4, gb = tid & 15;           // gate mapping (tid < 64)

    unsigned long long wp[12][4];
#pragma unroll
    for (int r = 0; r < 12; r++){
        const uint4* p = (const uint4*)&w_hh[(size_t)((r>>2)*512 + j0 + (r&3))*512 + kbase];
        uint4 q0 = p[0], q1 = p[1];
        wp[r][0] = pk2(q0.x, q0.y); wp[r][1] = pk2(q0.z, q0.w);
        wp[r][2] = pk2(q1.x, q1.y); wp[r][3] = pk2(q1.z, q1.w);
    }
    float brr = 0.f, bzz = 0.f, bnn = 0.f, xr = 0.f, xz = 0.f, xn = 0.f;
    if (tid < 64){
        brr = b_hh[j0 + gu]; bzz = b_hh[512 + j0 + gu]; bnn = b_hh[1024 + j0 + gu];
        const float* xp = &g_xp[(size_t)gb*1536 + j0 + gu];   // t = 0
        xr = __ldg(xp); xz = __ldg(xp + 512); xn = __ldg(xp + 1024);
    }

    for (int t = 0; t < TT; t++){
        const float* hb = g_hbuf[t & 1];
        unsigned long long hp[4][4];
#pragma unroll
        for (int b = 0; b < 4; b++){
            const uint4* p = (const uint4*)&hb[(bg*4 + b)*512 + kbase];
            uint4 q0 = __ldcg(p), q1 = __ldcg(p + 1);
            hp[b][0] = pk2(q0.x, q0.y); hp[b][1] = pk2(q0.z, q0.w);
            hp[b][2] = pk2(q1.x, q1.y); hp[b][3] = pk2(q1.z, q1.w);
        }
        float hold = 0.f;
        if (tid < 64) hold = __ldcg(&hb[gb*512 + j0 + gu]);

#pragma unroll
        for (int r = 0; r < 12; r++)
#pragma unroll
            for (int b = 0; b < 4; b++){
                unsigned long long a2;
                asm("mul.rn.f32x2 %0, %1, %2;"     : "=l"(a2) : "l"(wp[r][0]), "l"(hp[b][0]));
                asm("fma.rn.f32x2 %0, %1, %2, %0;" : "+l"(a2) : "l"(wp[r][1]), "l"(hp[b][1]));
                asm("fma.rn.f32x2 %0, %1, %2, %0;" : "+l"(a2) : "l"(wp[r][2]), "l"(hp[b][2]));
                asm("fma.rn.f32x2 %0, %1, %2, %0;" : "+l"(a2) : "l"(wp[r][3]), "l"(hp[b][3]));
                float lo, hi;
                asm("mov.b64 {%0, %1}, %2;" : "=f"(lo), "=f"(hi) : "l"(a2));
                float v = lo + hi;
                v += __shfl_xor_sync(0xffffffffu, v, 1);
                v += __shfl_xor_sync(0xffffffffu, v, 2);
                if ((lane & 3) == 0)
                    part[kh*1536 + r*128 + (bg*4 + b)*8 + (lane >> 2)] = v;
            }
        __syncthreads();

        if (tid < 64){
            float d[3];
#pragma unroll
            for (int g = 0; g < 3; g++){
                int rowp = g*4 + gu;
                const float4* p0 = (const float4*)&part[rowp*128 + gb*8];
                const float4* p1 = (const float4*)&part[1536 + rowp*128 + gb*8];
                float4 a = p0[0], b4 = p0[1], c = p1[0], e = p1[1];
                d[g] = ((a.x + a.y) + (a.z + a.w)) + ((b4.x + b4.y) + (b4.z + b4.w))
                     + ((c.x + c.y) + (c.z + c.w)) + ((e.x + e.y) + (e.z + e.w));
            }
            float rg = 1.f/(1.f + expf(-(xr + d[0] + brr)));
            float zg = 1.f/(1.f + expf(-(xz + d[1] + bzz)));
            float ng = tanhf(xn + rg*(d[2] + bnn));
            float hnew = (1.f - zg)*ng + zg*hold;
            g_hbuf[(t + 1) & 1][gb*512 + j0 + gu] = hnew;
            g_hs[((size_t)t*16 + gb)*512 + j0 + gu] = hnew;
            int tn = (t + 1 < TT) ? t + 1 : t;
            const float* xp = &g_xp[(size_t)(tn*16 + gb)*1536 + j0 + gu];
            xr = __ldg(xp); xz = __ldg(xp + 512); xn = __ldg(xp + 1024);
        }
        __syncthreads();
        if (tid == 0){
            __threadfence();
            atomicAdd(&g_bar, 1u);
            unsigned tgt = (unsigned)(t + 1)*NCTA, v;
            while (true){
                asm volatile("ld.acquire.gpu.global.u32 %0, [%1];"
                             : "=r"(v) : "l"(&g_bar) : "memory");
                if (v >= tgt) break;
                __nanosleep(64);
            }
        }
        __syncthreads();
    }
}

// ---------------- launch ----------------------------------------------------
extern "C" void kernel_launch(void* const* d_in, const int* in_sizes, int n_in,
                              void* d_out, int out_size)
{
    const int*   x    = (const int*)  d_in[0];
    const float* mels = (const float*)d_in[1];
    const float* k0   = (const float*)d_in[2];
    const float* k1   = (const float*)d_in[3];
    const float* k2   = (const float*)d_in[4];
    const float* w_ih = (const float*)d_in[5];
    const float* w_hh = (const float*)d_in[6];
    const float* b_ih = (const float*)d_in[7];
    const float* b_hh = (const float*)d_in[8];
    const float* fc1w = (const float*)d_in[9];
    const float* fc1b = (const float*)d_in[10];
    const float* fc2w = (const float*)d_in[11];
    const float* fc2b = (const float*)d_in[12];
    float* out = (float*)d_out;

    pre_k<<<3072, 256>>>(mels, k0, k1, w_ih);                 // 1
    up3_k<<<16500, 256>>>(k2);                                // 2
    gemm_k<<<dim3(24, 825), 256>>>(0, w_ih, 592, 512, b_ih,   // 3: x_proj
                                   0, nullptr, 1536, 80, 0, 1, x);
    gru_k<<<NCTA, 256>>>(w_hh, b_hh);                         // 4  <- profiled slot
    gemm_k<<<dim3(8, 825), 256>>>(1, fc1w, 512, 0, fc1b,      // 5: fc1 (relu)
                                  1, nullptr, 512, 512, 1, 0, nullptr);
    gemm_k<<<dim3(8, 825), 256>>>(2, fc2w, 512, 0, fc2b,      // 6: fc2 (permuted out)
                                  2, out, 512, 512, 2, 0, nullptr);
}